// round 15
// baseline (speedup 1.0000x reference)
#include <cuda_runtime.h>
#include <cuda_fp16.h>
#include <cstdint>

#define NCELL 65536
#define TST   365
#define CPB   64
#define NBLK  (NCELL / CPB)

// smem byte offsets
#define H16   0        // h f16 tile: 2 bufs x 64 rows x 144B   = 18432
#define X16   18432    // x f16 tile: 2 bufs x 64 rows x 16B    =  2048
#define PTB   20480    // p,t fp32:   2 bufs x 64 x float2      =  1024
#define BYS   21504    // out_w f16x2 B-frags: 32 u32           =   128
#define SMB   21760

typedef unsigned int u32;
typedef unsigned short u16;

static __device__ __forceinline__ u32 s2u(const void* p) {
    u32 a;
    asm("{ .reg .u64 t; cvta.to.shared.u64 t, %1; cvt.u32.u64 %0, t; }"
        : "=r"(a) : "l"(p));
    return a;
}
static __device__ __forceinline__ u16 f2h(float f) {
    return __half_as_ushort(__float2half(f));
}
static __device__ __forceinline__ u32 pk(u16 a, u16 b) {
    return (u32)a | ((u32)b << 16);
}
static __device__ __forceinline__ float tanha(float x) {
    float r;
    asm("tanh.approx.f32 %0, %1;" : "=f"(r) : "f"(x));
    return r;
}
// packed sigmoid of an f16x2 pre-activation pair
static __device__ __forceinline__ float2 sigm2p(u32 x2) {
    u32 s, th;
    asm("mul.f16x2 %0, %1, %2;" : "=r"(s) : "r"(x2), "r"(0x38003800u));  // *0.5
    asm("tanh.approx.f16x2 %0, %1;" : "=r"(th) : "r"(s));
    __half2 h2 = *reinterpret_cast<__half2*>(&th);
    float2 f = __half22float2(h2);
    return make_float2(fmaf(f.x, 0.5f, 0.5f), fmaf(f.y, 0.5f, 0.5f));
}

#define LDSM4(R, ad) \
    asm volatile("ldmatrix.sync.aligned.m8n8.x4.shared.b16 {%0,%1,%2,%3}, [%4];" \
        : "=r"((R)[0]), "=r"((R)[1]), "=r"((R)[2]), "=r"((R)[3]) : "r"(ad) : "memory")
#define LDSM2(R, ad) \
    asm volatile("ldmatrix.sync.aligned.m8n8.x2.shared.b16 {%0,%1}, [%2];" \
        : "=r"((R)[0]), "=r"((R)[1]) : "r"(ad) : "memory")
#define HMMA16F(D, A, B0, B1) \
    asm("mma.sync.aligned.m16n8k16.row.col.f32.f16.f16.f32 " \
        "{%0,%1,%2,%3}, {%4,%5,%6,%7}, {%8,%9}, {%0,%1,%2,%3};" \
        : "+f"((D)[0]), "+f"((D)[1]), "+f"((D)[2]), "+f"((D)[3]) \
        : "r"((A)[0]), "r"((A)[1]), "r"((A)[2]), "r"((A)[3]), "r"(B0), "r"(B1))
#define HMMA8F(D, A, B0) \
    asm("mma.sync.aligned.m16n8k8.row.col.f32.f16.f16.f32 " \
        "{%0,%1,%2,%3}, {%4,%5}, {%6}, {%0,%1,%2,%3};" \
        : "+f"((D)[0]), "+f"((D)[1]), "+f"((D)[2]), "+f"((D)[3]) \
        : "r"((A)[0]), "r"((A)[1]), "r"(B0))
#define HMMA16H(D, A, B0, B1) \
    asm("mma.sync.aligned.m16n8k16.row.col.f16.f16.f16.f16 " \
        "{%0,%1}, {%2,%3,%4,%5}, {%6,%7}, {%0,%1};" \
        : "+r"((D)[0]), "+r"((D)[1]) \
        : "r"((A)[0]), "r"((A)[1]), "r"((A)[2]), "r"((A)[3]), "r"(B0), "r"(B1))
#define HMMA8H(D, A, B0) \
    asm("mma.sync.aligned.m16n8k8.row.col.f16.f16.f16.f16 " \
        "{%0,%1}, {%2,%3}, {%4}, {%0,%1};" \
        : "+r"((D)[0]), "+r"((D)[1]) \
        : "r"((A)[0]), "r"((A)[1]), "r"(B0))

__global__ void __launch_bounds__(256, 2)
gru_f16_kernel(const float* __restrict__ precip, const float* __restrict__ temp,
               const float* __restrict__ w_ih, const float* __restrict__ w_hh,
               const float* __restrict__ bias, const float* __restrict__ bias_n,
               const float* __restrict__ out_w, const float* __restrict__ out_b,
               const float* __restrict__ init_h, float* __restrict__ out) {
    extern __shared__ char sm[];
    const u32 sb = s2u(sm);
    u16*  h16  = (u16*)(sm + H16);           // two 4608-u16 buffers
    float2* ptb = (float2*)(sm + PTB);
    u32* bys = (u32*)(sm + BYS);

    const int tid  = threadIdx.x;
    const int wid  = tid >> 5;
    const int lane = tid & 31;
    const int g    = lane >> 2;
    const int c4   = lane & 3;
    const int k0   = 8 * wid + 2 * c4;
    const int cellbase = blockIdx.x * CPB;
    const int scell = wid * 8 + (lane & 7);  // staging cell (lane<8 active)

    // ---- W_hh register fragments (rounded f16) ----
    u32 Bh[3][4][2];
#pragma unroll
    for (int grp = 0; grp < 3; ++grp) {
        const float* wr = w_hh + (grp * 64 + 8 * wid + g) * 64;
#pragma unroll
        for (int c = 0; c < 4; ++c)
#pragma unroll
            for (int rr = 0; rr < 2; ++rr) {
                int kk = c * 16 + rr * 8 + 2 * c4;
                Bh[grp][c][rr] = pk(f2h(wr[kk]), f2h(wr[kk + 1]));
            }
    }
    // ---- x-chunk B frags: r,z carry (w_p,w_t | bias); n carries (0 | bias_n) ----
    u32 Bx[3];
#pragma unroll
    for (int grp = 0; grp < 2; ++grp) {
        int gate = grp * 64 + 8 * wid + g;
        u32 v = 0;
        if (c4 == 0)      v = pk(f2h(w_ih[gate * 2]), f2h(w_ih[gate * 2 + 1]));
        else if (c4 == 1) v = pk(f2h(bias[gate]), 0);
        Bx[grp] = v;
    }
    {
        u32 v = 0;
        if (c4 == 1) v = pk(f2h(bias_n[8 * wid + g]), 0);
        Bx[2] = v;
    }
    // ---- out_w B-frags (col 0 only) into smem ----
    if (tid < 32) {
        int c = tid >> 3, rr = (tid >> 2) & 1, q = tid & 3;
        int kk = c * 16 + rr * 8 + 2 * q;
        bys[c * 8 + rr * 4 + q] = pk(f2h(out_w[kk]), f2h(out_w[kk + 1]));
    }
    // ---- exact scalars for candidate gate ----
    const float wp0 = w_ih[(128 + k0) * 2],     wt0 = w_ih[(128 + k0) * 2 + 1];
    const float wp1 = w_ih[(128 + k0 + 1) * 2], wt1 = w_ih[(128 + k0 + 1) * 2 + 1];
    const float bb0 = bias[128 + k0], bb1 = bias[128 + k0 + 1];
    const float ob  = out_b[0];

    // ---- h state: fp32 in regs ----
    float hreg[16];
#pragma unroll
    for (int u = 0; u < 16; ++u) hreg[u] = init_h[k0 + (u & 1)];
    for (int idx = tid; idx < 64 * 64; idx += 256)
        h16[(idx >> 6) * 72 + (idx & 63)] = f2h(init_h[idx & 63]);
    // x buf 0 (t=0) + pt buf 0; prefetch t=1 (lane<8 per warp)
    float pv = 0.f, tv = 0.f;
    if (lane < 8) {
        float p0 = precip[cellbase + scell], t0 = temp[cellbase + scell];
        *(uint4*)(sm + X16 + scell * 16) =
            make_uint4(pk(f2h(p0), f2h(t0)), pk(0x3C00, 0), 0, 0);  // 1.0h
        ptb[scell] = make_float2(p0, t0);
        pv = precip[NCELL + cellbase + scell];
        tv = temp[NCELL + cellbase + scell];
    }
    __syncthreads();

    const u32 ah_lm = sb + H16 + (u32)((lane & 15) * 144 + (lane >> 4) * 16);
    const u32 ax_lm = sb + X16 + (u32)((lane & 15) * 16);

    // ---- phase stagger: odd co-resident CTAs burn ~1 MMA-phase once ----
    if ((blockIdx.x / 148) & 1) {
        u32 dd[2] = {0u, 0u};
#pragma unroll
        for (int j = 0; j < 2; ++j)
#pragma unroll
            for (int c = 0; c < 4; ++c) {
                u32 a[4];
                LDSM4(a, ah_lm + (u32)(c * 32));
                HMMA16H(dd, a, Bh[0][c][0], Bh[0][c][1]);
                HMMA16H(dd, a, Bh[1][c][0], Bh[1][c][1]);
                HMMA16H(dd, a, Bh[2][c][0], Bh[2][c][1]);
            }
        // keep live; lands in X16 buf1, overwritten by t=0 staging before use
        *(u32*)(sm + X16 + 1024 + (tid & 63) * 16 + 8) = dd[0] ^ dd[1];
    }

    for (int t = 0; t < TST; ++t) {
        const int pr = t & 1, nx = (t + 1) & 1;

        // ---- staging (lane<8): x(t+1), pt(t+1), prefetch(t+2) ----
        if (lane < 8) {
            *(uint4*)(sm + X16 + nx * 1024 + scell * 16) =
                make_uint4(pk(f2h(pv), f2h(tv)), pk(0x3C00, 0), 0, 0);
            ptb[nx * CPB + scell] = make_float2(pv, tv);
            int tn = (t + 2 < TST) ? t + 2 : TST - 1;
            pv = precip[tn * NCELL + cellbase + scell];
            tv = temp[tn * NCELL + cellbase + scell];
        }

        // ---- MMA: reads hbuf[pr], xbuf[pr] ----
        u32  drz[4][2][2];   // f16x2 accum: [mt][r|z][hf]
        float dn[4][4];      // f32 accum
        u32  dy[2] = {0u, 0u};  // f16x2 accum, y col (warps 0-3, mt = wid)
#pragma unroll
        for (int mt = 0; mt < 4; ++mt) {
            drz[mt][0][0] = drz[mt][0][1] = 0u;
            drz[mt][1][0] = drz[mt][1][1] = 0u;
            dn[mt][0] = dn[mt][1] = dn[mt][2] = dn[mt][3] = 0.f;
        }
        const u32 ah_b = ah_lm + (u32)(pr * 9216);
        const u32 ax_b = ax_lm + (u32)(pr * 1024);
#pragma unroll
        for (int c = 0; c < 4; ++c) {
            u32 by0 = 0, by1 = 0;
            if (wid < 4 && g == 0) {
                by0 = bys[c * 8 + c4];
                by1 = bys[c * 8 + 4 + c4];
            }
            u32 a[4][4];
#pragma unroll
            for (int mt = 0; mt < 4; ++mt)
                LDSM4(a[mt], ah_b + mt * 2304 + c * 32);
#pragma unroll
            for (int mt = 0; mt < 4; ++mt) {
                HMMA16H(drz[mt][0], a[mt], Bh[0][c][0], Bh[0][c][1]);
                HMMA16H(drz[mt][1], a[mt], Bh[1][c][0], Bh[1][c][1]);
                HMMA16F(dn[mt],     a[mt], Bh[2][c][0], Bh[2][c][1]);
                if (wid == mt)      // y column: warp w handles mt = w
                    HMMA16H(dy, a[mt], by0, by1);
            }
        }
#pragma unroll
        for (int mt = 0; mt < 4; ++mt) {
            u32 ax[2];
            LDSM2(ax, ax_b + mt * 256);
            HMMA8H(drz[mt][0], ax, Bx[0]);
            HMMA8H(drz[mt][1], ax, Bx[1]);
            HMMA8F(dn[mt],     ax, Bx[2]);     // bias_n into candidate pre-act
        }

        // ---- y(t-1) = out_w . h_{t-1} (+ out_b), from MMA ----
        if (wid < 4 && c4 == 0 && t > 0) {
            __half2 a0 = *reinterpret_cast<__half2*>(&dy[0]);
            __half2 a1 = *reinterpret_cast<__half2*>(&dy[1]);
            float* yo = out + (long long)(t - 1) * NCELL + cellbase + wid * 16 + g;
            yo[0] = __low2float(a0) + ob;
            yo[8] = __low2float(a1) + ob;
        }

        // ---- epilogue: writes hbuf[nx] ----
        u16* h16w = h16 + nx * 4608;
        const float2* ptc = ptb + pr * CPB;
#pragma unroll
        for (int mt = 0; mt < 4; ++mt) {
#pragma unroll
            for (int hf = 0; hf < 2; ++hf) {
                const int cell = mt * 16 + g + hf * 8;
                const int u = mt * 4 + hf * 2;
                float2 xv = ptc[cell];
                float2 rr = sigm2p(drz[mt][0][hf]);
                float2 zz = sigm2p(drz[mt][1][hf]);
                float Dn0 = dn[mt][2 * hf], Dn1 = dn[mt][2 * hf + 1];
                float ig0 = fmaf(wp0, xv.x, fmaf(wt0, xv.y, bb0));
                float ig1 = fmaf(wp1, xv.x, fmaf(wt1, xv.y, bb1));
                float n0 = tanha(fmaf(rr.x, Dn0, ig0));
                float n1 = tanha(fmaf(rr.y, Dn1, ig1));
                float h0 = fmaf(zz.x, hreg[u] - n0, n0);
                float h1 = fmaf(zz.y, hreg[u + 1] - n1, n1);
                hreg[u] = h0; hreg[u + 1] = h1;
                *(u32*)&h16w[cell * 72 + k0] = pk(f2h(h0), f2h(h1));
            }
        }
        __syncthreads();   // single barrier per step
    }

    // ---- final y (t = TST-1) from exact hreg, via shfl + smem scratch ----
    {
        float* ysc = (float*)(sm + H16);   // hbuf0 is dead (final h is in buf1/hreg)
        const float ow0f = out_w[k0], ow1f = out_w[k0 + 1];
        __syncthreads();
#pragma unroll
        for (int mt = 0; mt < 4; ++mt)
#pragma unroll
            for (int hf = 0; hf < 2; ++hf) {
                const int cell = mt * 16 + g + hf * 8;
                const int u = mt * 4 + hf * 2;
                float yq = fmaf(ow0f, hreg[u], ow1f * hreg[u + 1]);
                yq += __shfl_xor_sync(0xffffffffu, yq, 1);
                yq += __shfl_xor_sync(0xffffffffu, yq, 2);
                if (c4 == 0) ysc[wid * CPB + cell] = yq;
            }
        __syncthreads();
        if (tid < CPB) {
            float y = ob;
#pragma unroll
            for (int w = 0; w < 8; ++w) y += ysc[w * CPB + tid];
            out[(TST - 1) * NCELL + cellbase + tid] = y;
        }
    }

    // ---- final hidden state (exact fp32 from regs) ----
#pragma unroll
    for (int u = 0; u < 16; ++u) {
        int cell = (u >> 2) * 16 + g + ((u >> 1) & 1) * 8;
        int k = k0 + (u & 1);
        out[(long long)TST * NCELL + (long long)(cellbase + cell) * 64 + k] = hreg[u];
    }
}

extern "C" void kernel_launch(void* const* d_in, const int* in_sizes, int n_in,
                              void* d_out, int out_size) {
    const float* precip = (const float*)d_in[0];
    const float* temp   = (const float*)d_in[1];
    const float* w_ih   = (const float*)d_in[2];
    const float* w_hh   = (const float*)d_in[3];
    const float* bias   = (const float*)d_in[4];
    const float* bias_n = (const float*)d_in[5];
    const float* out_w  = (const float*)d_in[6];
    const float* out_b  = (const float*)d_in[7];
    const float* init_h = (const float*)d_in[8];
    float* out = (float*)d_out;

    gru_f16_kernel<<<NBLK, 256, SMB>>>(
        precip, temp, w_ih, w_hh, bias, bias_n, out_w, out_b, init_h, out);
}

// round 16
// speedup vs baseline: 1.0181x; 1.0181x over previous
#include <cuda_runtime.h>
#include <cuda_fp16.h>
#include <cstdint>

#define NCELL 65536
#define TST   365
#define CPB   64
#define NBLK  (NCELL / CPB)

// smem byte offsets
#define H16   0        // h f16 tile: 2 bufs x 64 rows x 144B   = 18432
#define X16   18432    // x f16 tile: 2 bufs x 64 rows x 16B    =  2048
#define PTB   20480    // p,t fp32:   2 bufs x 64 x float2      =  1024
#define YPT   21504    // y partials: 2 bufs x 8 x 64 f32       =  4096
#define SMB   25600

typedef unsigned int u32;
typedef unsigned short u16;

static __device__ __forceinline__ u32 s2u(const void* p) {
    u32 a;
    asm("{ .reg .u64 t; cvta.to.shared.u64 t, %1; cvt.u32.u64 %0, t; }"
        : "=r"(a) : "l"(p));
    return a;
}
static __device__ __forceinline__ u16 f2h(float f) {
    return __half_as_ushort(__float2half(f));
}
static __device__ __forceinline__ u32 pk(u16 a, u16 b) {
    return (u32)a | ((u32)b << 16);
}
static __device__ __forceinline__ float tanha(float x) {
    float r;
    asm("tanh.approx.f32 %0, %1;" : "=f"(r) : "f"(x));
    return r;
}
// packed sigmoid of two fp32 pre-activations via one f16x2 tanh MUFU
static __device__ __forceinline__ float2 sigm2_fast(float x0, float x1) {
    u32 p, s, th;
    asm("cvt.rn.f16x2.f32 %0, %1, %2;" : "=r"(p) : "f"(x1), "f"(x0)); // lo=x0,hi=x1
    asm("mul.f16x2 %0, %1, %2;" : "=r"(s) : "r"(p), "r"(0x38003800u)); // * 0.5
    asm("tanh.approx.f16x2 %0, %1;" : "=r"(th) : "r"(s));
    __half2 h2 = *reinterpret_cast<__half2*>(&th);
    float2 f = __half22float2(h2);
    return make_float2(fmaf(f.x, 0.5f, 0.5f), fmaf(f.y, 0.5f, 0.5f));
}

#define LDSM4(R, ad) \
    asm volatile("ldmatrix.sync.aligned.m8n8.x4.shared.b16 {%0,%1,%2,%3}, [%4];" \
        : "=r"((R)[0]), "=r"((R)[1]), "=r"((R)[2]), "=r"((R)[3]) : "r"(ad) : "memory")
#define LDSM2(R, ad) \
    asm volatile("ldmatrix.sync.aligned.m8n8.x2.shared.b16 {%0,%1}, [%2];" \
        : "=r"((R)[0]), "=r"((R)[1]) : "r"(ad) : "memory")
#define HMMA16(D, A, B0, B1) \
    asm("mma.sync.aligned.m16n8k16.row.col.f32.f16.f16.f32 " \
        "{%0,%1,%2,%3}, {%4,%5,%6,%7}, {%8,%9}, {%0,%1,%2,%3};" \
        : "+f"((D)[0]), "+f"((D)[1]), "+f"((D)[2]), "+f"((D)[3]) \
        : "r"((A)[0]), "r"((A)[1]), "r"((A)[2]), "r"((A)[3]), "r"(B0), "r"(B1))
#define HMMA8(D, A, B0) \
    asm("mma.sync.aligned.m16n8k8.row.col.f32.f16.f16.f32 " \
        "{%0,%1,%2,%3}, {%4,%5}, {%6}, {%0,%1,%2,%3};" \
        : "+f"((D)[0]), "+f"((D)[1]), "+f"((D)[2]), "+f"((D)[3]) \
        : "r"((A)[0]), "r"((A)[1]), "r"(B0))

__global__ void __launch_bounds__(256, 2)
gru_f16_kernel(const float* __restrict__ precip, const float* __restrict__ temp,
               const float* __restrict__ w_ih, const float* __restrict__ w_hh,
               const float* __restrict__ bias, const float* __restrict__ bias_n,
               const float* __restrict__ out_w, const float* __restrict__ out_b,
               const float* __restrict__ init_h, float* __restrict__ out) {
    extern __shared__ char sm[];
    const u32 sb = s2u(sm);
    u16*  h16  = (u16*)(sm + H16);           // two 4608-u16 buffers
    float2* ptb = (float2*)(sm + PTB);
    float* ybuf = (float*)(sm + YPT);

    const int tid  = threadIdx.x;
    const int wid  = tid >> 5;
    const int lane = tid & 31;
    const int g    = lane >> 2;
    const int c4   = lane & 3;
    const int k0   = 8 * wid + 2 * c4;
    const int cellbase = blockIdx.x * CPB;

    // ---- W_hh register fragments (rounded f16) ----
    u32 Bh[3][4][2];
#pragma unroll
    for (int grp = 0; grp < 3; ++grp) {
        const float* wr = w_hh + (grp * 64 + 8 * wid + g) * 64;
#pragma unroll
        for (int c = 0; c < 4; ++c)
#pragma unroll
            for (int rr = 0; rr < 2; ++rr) {
                int kk = c * 16 + rr * 8 + 2 * c4;
                Bh[grp][c][rr] = pk(f2h(wr[kk]), f2h(wr[kk + 1]));
            }
    }
    // ---- x-chunk B frags: r,z carry (w_p,w_t | bias); n carries (0 | bias_n) ----
    u32 Bx[3];
#pragma unroll
    for (int grp = 0; grp < 2; ++grp) {
        int gate = grp * 64 + 8 * wid + g;
        u32 v = 0;
        if (c4 == 0)      v = pk(f2h(w_ih[gate * 2]), f2h(w_ih[gate * 2 + 1]));
        else if (c4 == 1) v = pk(f2h(bias[gate]), 0);
        Bx[grp] = v;
    }
    {
        u32 v = 0;
        if (c4 == 1) v = pk(f2h(bias_n[8 * wid + g]), 0);
        Bx[2] = v;
    }
    // ---- exact scalars for candidate gate + output ----
    const float wp0 = w_ih[(128 + k0) * 2],     wt0 = w_ih[(128 + k0) * 2 + 1];
    const float wp1 = w_ih[(128 + k0 + 1) * 2], wt1 = w_ih[(128 + k0 + 1) * 2 + 1];
    const float bb0 = bias[128 + k0], bb1 = bias[128 + k0 + 1];
    const float ow0 = out_w[k0],      ow1 = out_w[k0 + 1];
    const float ob  = out_b[0];

    // ---- h state: fp32 in regs (thread owns fixed (cell,k) pairs) ----
    float hreg[16];
#pragma unroll
    for (int u = 0; u < 16; ++u) hreg[u] = init_h[k0 + (u & 1)];
    // h buffer 0 init
    for (int idx = tid; idx < 64 * 64; idx += 256)
        h16[(idx >> 6) * 72 + (idx & 63)] = f2h(init_h[idx & 63]);
    // x buf 0 (t=0) + pt buf 0; prefetch t=1
    float pv = 0.f, tv = 0.f;
    if (tid < CPB) {
        float p0 = precip[cellbase + tid], t0 = temp[cellbase + tid];
        *(uint4*)(sm + X16 + tid * 16) =
            make_uint4(pk(f2h(p0), f2h(t0)), pk(0x3C00, 0), 0, 0);  // 1.0h
        ptb[tid] = make_float2(p0, t0);
        pv = precip[NCELL + cellbase + tid];
        tv = temp[NCELL + cellbase + tid];
    }
    __syncthreads();

    const u32 ah_lm = sb + H16 + (u32)((lane & 15) * 144 + (lane >> 4) * 16);
    const u32 ax_lm = sb + X16 + (u32)((lane & 15) * 16);

    // ---- phase stagger: odd co-resident CTA burns ~half a step window ONCE ----
    // Co-residency on an SM pairs bid with bid+148 (classic launch, 2 CTAs/SM);
    // identical per-step work keeps the offset invariant for all 365 steps.
    if ((blockIdx.x / 148) & 1) {
        float dd[4] = {0.f, 0.f, 0.f, 0.f};
        for (int rep = 0; rep < 10; ++rep) {       // ~10 x ~190cyc ≈ half window
#pragma unroll
            for (int c = 0; c < 4; ++c) {
                u32 a[4];
                LDSM4(a, ah_lm + (u32)(c * 32));
                HMMA16(dd, a, Bh[0][c][0], Bh[0][c][1]);
                HMMA16(dd, a, Bh[1][c][0], Bh[1][c][1]);
                HMMA16(dd, a, Bh[2][c][0], Bh[2][c][1]);
            }
        }
        // sink (kept live): lands in xbuf[1], fully overwritten by t=0 staging
        *(float*)(sm + X16 + 1024 + (tid & 63) * 16 + 8) = dd[0] + dd[1] + dd[2] + dd[3];
    }

    for (int t = 0; t < TST; ++t) {
        const int pr = t & 1, nx = (t + 1) & 1;
        float d[4][3][4];
#pragma unroll
        for (int mt = 0; mt < 4; ++mt)
#pragma unroll
            for (int gr = 0; gr < 3; ++gr)
#pragma unroll
                for (int q = 0; q < 4; ++q) d[mt][gr][q] = 0.f;

        // ---- MMA: reads hbuf[pr], xbuf[pr] ----
        const u32 ah_b = ah_lm + (u32)(pr * 9216);
        const u32 ax_b = ax_lm + (u32)(pr * 1024);
#pragma unroll
        for (int c = 0; c < 4; ++c) {
            u32 a[4][4];
#pragma unroll
            for (int mt = 0; mt < 4; ++mt)
                LDSM4(a[mt], ah_b + mt * 2304 + c * 32);
#pragma unroll
            for (int mt = 0; mt < 4; ++mt) {
                HMMA16(d[mt][0], a[mt], Bh[0][c][0], Bh[0][c][1]);
                HMMA16(d[mt][1], a[mt], Bh[1][c][0], Bh[1][c][1]);
                HMMA16(d[mt][2], a[mt], Bh[2][c][0], Bh[2][c][1]);
            }
        }
#pragma unroll
        for (int mt = 0; mt < 4; ++mt) {
            u32 ax[2];
            LDSM2(ax, ax_b + mt * 256);
            HMMA8(d[mt][0], ax, Bx[0]);
            HMMA8(d[mt][1], ax, Bx[1]);
            HMMA8(d[mt][2], ax, Bx[2]);       // adds bias_n to candidate pre-act
        }

        // ---- staging warps: x(t+1), pt(t+1), y-reduce(t-1), prefetch(t+2) ----
        if (tid < CPB) {
            *(uint4*)(sm + X16 + nx * 1024 + tid * 16) =
                make_uint4(pk(f2h(pv), f2h(tv)), pk(0x3C00, 0), 0, 0);
            ptb[nx * CPB + tid] = make_float2(pv, tv);
            int tn = (t + 2 < TST) ? t + 2 : TST - 1;
            pv = precip[tn * NCELL + cellbase + tid];
            tv = temp[tn * NCELL + cellbase + tid];
            if (t > 0) {
                float y = ob;
                const float* yb = ybuf + ((t - 1) & 1) * 512;
#pragma unroll
                for (int w = 0; w < 8; ++w) y += yb[w * CPB + tid];
                out[(t - 1) * NCELL + cellbase + tid] = y;
            }
        }

        // ---- epilogue: writes hbuf[nx] (disjoint from MMA reads), ybuf[pr] ----
        u16* h16w = h16 + nx * 4608;
        const float2* ptc = ptb + pr * CPB;
        float* yb = ybuf + pr * 512;
#pragma unroll
        for (int mt = 0; mt < 4; ++mt) {
#pragma unroll
            for (int hf = 0; hf < 2; ++hf) {
                const int cell = mt * 16 + g + hf * 8;
                const int u = mt * 4 + hf * 2;
                float2 xv = ptc[cell];
                float Dr0 = d[mt][0][2 * hf], Dr1 = d[mt][0][2 * hf + 1];
                float Dz0 = d[mt][1][2 * hf], Dz1 = d[mt][1][2 * hf + 1];
                float Dn0 = d[mt][2][2 * hf], Dn1 = d[mt][2][2 * hf + 1];
                float2 rr = sigm2_fast(Dr0, Dr1);
                float2 zz = sigm2_fast(Dz0, Dz1);
                float ig0 = fmaf(wp0, xv.x, fmaf(wt0, xv.y, bb0));
                float ig1 = fmaf(wp1, xv.x, fmaf(wt1, xv.y, bb1));
                float n0 = tanha(fmaf(rr.x, Dn0, ig0));   // bn already in Dn
                float n1 = tanha(fmaf(rr.y, Dn1, ig1));
                float h0 = fmaf(zz.x, hreg[u] - n0, n0);
                float h1 = fmaf(zz.y, hreg[u + 1] - n1, n1);
                hreg[u] = h0; hreg[u + 1] = h1;
                *(u32*)&h16w[cell * 72 + k0] = pk(f2h(h0), f2h(h1));
                float yq = fmaf(ow0, h0, ow1 * h1);
                yq += __shfl_xor_sync(0xffffffffu, yq, 1);
                yq += __shfl_xor_sync(0xffffffffu, yq, 2);
                if (c4 == 0) yb[wid * CPB + cell] = yq;
            }
        }
        __syncthreads();   // single barrier per step
    }

    // trailing y reduce for t = TST-1
    if (tid < CPB) {
        float y = ob;
        const float* yb = ybuf + ((TST - 1) & 1) * 512;
#pragma unroll
        for (int w = 0; w < 8; ++w) y += yb[w * CPB + tid];
        out[(TST - 1) * NCELL + cellbase + tid] = y;
    }

    // ---- final hidden state (exact fp32 from regs) ----
#pragma unroll
    for (int u = 0; u < 16; ++u) {
        int cell = (u >> 2) * 16 + g + ((u >> 1) & 1) * 8;
        int k = k0 + (u & 1);
        out[(long long)TST * NCELL + (long long)(cellbase + cell) * 64 + k] = hreg[u];
    }
}

extern "C" void kernel_launch(void* const* d_in, const int* in_sizes, int n_in,
                              void* d_out, int out_size) {
    const float* precip = (const float*)d_in[0];
    const float* temp   = (const float*)d_in[1];
    const float* w_ih   = (const float*)d_in[2];
    const float* w_hh   = (const float*)d_in[3];
    const float* bias   = (const float*)d_in[4];
    const float* bias_n = (const float*)d_in[5];
    const float* out_w  = (const float*)d_in[6];
    const float* out_b  = (const float*)d_in[7];
    const float* init_h = (const float*)d_in[8];
    float* out = (float*)d_out;

    gru_f16_kernel<<<NBLK, 256, SMB>>>(
        precip, temp, w_ih, w_hh, bias, bias_n, out_w, out_b, init_h, out);
}

// round 17
// speedup vs baseline: 1.0404x; 1.0220x over previous
#include <cuda_runtime.h>
#include <cuda_fp16.h>
#include <cstdint>

#define NCELL 65536
#define TST   365
#define CPB   64
#define NBLK  (NCELL / CPB)

// smem byte offsets
#define H16   0        // h f16 tile: 2 bufs x 64 rows x 144B   = 18432
#define X16   18432    // x f16 tile: 2 bufs x 64 rows x 16B    =  2048
#define PTB   20480    // p,t fp32:   2 bufs x 64 x float2      =  1024
#define YPT   21504    // y partials: 2 bufs x 8 x 64 f32       =  4096
#define SMB   25600

typedef unsigned int u32;
typedef unsigned short u16;

static __device__ __forceinline__ u32 s2u(const void* p) {
    u32 a;
    asm("{ .reg .u64 t; cvta.to.shared.u64 t, %1; cvt.u32.u64 %0, t; }"
        : "=r"(a) : "l"(p));
    return a;
}
static __device__ __forceinline__ u16 f2h(float f) {
    return __half_as_ushort(__float2half(f));
}
static __device__ __forceinline__ u32 pk(u16 a, u16 b) {
    return (u32)a | ((u32)b << 16);
}
static __device__ __forceinline__ float tanha(float x) {
    float r;
    asm("tanh.approx.f32 %0, %1;" : "=f"(r) : "f"(x));
    return r;
}
// packed sigmoid of two fp32 pre-activations via one f16x2 tanh MUFU
static __device__ __forceinline__ float2 sigm2_fast(float x0, float x1) {
    u32 p, s, th;
    asm("cvt.rn.f16x2.f32 %0, %1, %2;" : "=r"(p) : "f"(x1), "f"(x0)); // lo=x0,hi=x1
    asm("mul.f16x2 %0, %1, %2;" : "=r"(s) : "r"(p), "r"(0x38003800u)); // * 0.5
    asm("tanh.approx.f16x2 %0, %1;" : "=r"(th) : "r"(s));
    __half2 h2 = *reinterpret_cast<__half2*>(&th);
    float2 f = __half22float2(h2);
    return make_float2(fmaf(f.x, 0.5f, 0.5f), fmaf(f.y, 0.5f, 0.5f));
}

#define LDSM4(R, ad) \
    asm volatile("ldmatrix.sync.aligned.m8n8.x4.shared.b16 {%0,%1,%2,%3}, [%4];" \
        : "=r"((R)[0]), "=r"((R)[1]), "=r"((R)[2]), "=r"((R)[3]) : "r"(ad) : "memory")
#define LDSM2(R, ad) \
    asm volatile("ldmatrix.sync.aligned.m8n8.x2.shared.b16 {%0,%1}, [%2];" \
        : "=r"((R)[0]), "=r"((R)[1]) : "r"(ad) : "memory")
#define HMMA16(D, A, B0, B1) \
    asm("mma.sync.aligned.m16n8k16.row.col.f32.f16.f16.f32 " \
        "{%0,%1,%2,%3}, {%4,%5,%6,%7}, {%8,%9}, {%0,%1,%2,%3};" \
        : "+f"((D)[0]), "+f"((D)[1]), "+f"((D)[2]), "+f"((D)[3]) \
        : "r"((A)[0]), "r"((A)[1]), "r"((A)[2]), "r"((A)[3]), "r"(B0), "r"(B1))
#define HMMA8(D, A, B0) \
    asm("mma.sync.aligned.m16n8k8.row.col.f32.f16.f16.f32 " \
        "{%0,%1,%2,%3}, {%4,%5}, {%6}, {%0,%1,%2,%3};" \
        : "+f"((D)[0]), "+f"((D)[1]), "+f"((D)[2]), "+f"((D)[3]) \
        : "r"((A)[0]), "r"((A)[1]), "r"(B0))

__global__ void __launch_bounds__(256, 2)
gru_f16_kernel(const float* __restrict__ precip, const float* __restrict__ temp,
               const float* __restrict__ w_ih, const float* __restrict__ w_hh,
               const float* __restrict__ bias, const float* __restrict__ bias_n,
               const float* __restrict__ out_w, const float* __restrict__ out_b,
               const float* __restrict__ init_h, float* __restrict__ out) {
    extern __shared__ char sm[];
    const u32 sb = s2u(sm);
    u16*  h16  = (u16*)(sm + H16);           // two 4608-u16 buffers
    float2* ptb = (float2*)(sm + PTB);
    float* ybuf = (float*)(sm + YPT);

    const int tid  = threadIdx.x;
    const int wid  = tid >> 5;
    const int lane = tid & 31;
    const int g    = lane >> 2;
    const int c4   = lane & 3;
    const int k0   = 8 * wid + 2 * c4;
    const int cellbase = blockIdx.x * CPB;

    // ---- W_hh register fragments (rounded f16) ----
    u32 Bh[3][4][2];
#pragma unroll
    for (int grp = 0; grp < 3; ++grp) {
        const float* wr = w_hh + (grp * 64 + 8 * wid + g) * 64;
#pragma unroll
        for (int c = 0; c < 4; ++c)
#pragma unroll
            for (int rr = 0; rr < 2; ++rr) {
                int kk = c * 16 + rr * 8 + 2 * c4;
                Bh[grp][c][rr] = pk(f2h(wr[kk]), f2h(wr[kk + 1]));
            }
    }
    // ---- x-chunk B frags: r,z carry (w_p,w_t | bias); n carries (0 | bias_n) ----
    u32 Bx[3];
#pragma unroll
    for (int grp = 0; grp < 2; ++grp) {
        int gate = grp * 64 + 8 * wid + g;
        u32 v = 0;
        if (c4 == 0)      v = pk(f2h(w_ih[gate * 2]), f2h(w_ih[gate * 2 + 1]));
        else if (c4 == 1) v = pk(f2h(bias[gate]), 0);
        Bx[grp] = v;
    }
    {
        u32 v = 0;
        if (c4 == 1) v = pk(f2h(bias_n[8 * wid + g]), 0);
        Bx[2] = v;
    }
    // ---- exact scalars for candidate gate + output ----
    const float wp0 = w_ih[(128 + k0) * 2],     wt0 = w_ih[(128 + k0) * 2 + 1];
    const float wp1 = w_ih[(128 + k0 + 1) * 2], wt1 = w_ih[(128 + k0 + 1) * 2 + 1];
    const float bb0 = bias[128 + k0], bb1 = bias[128 + k0 + 1];
    const float ow0 = out_w[k0],      ow1 = out_w[k0 + 1];
    const float ob  = out_b[0];

    // ---- h state: fp32 in regs (thread owns fixed (cell,k) pairs) ----
    float hreg[16];
#pragma unroll
    for (int u = 0; u < 16; ++u) hreg[u] = init_h[k0 + (u & 1)];
    // h buffer 0 init
    for (int idx = tid; idx < 64 * 64; idx += 256)
        h16[(idx >> 6) * 72 + (idx & 63)] = f2h(init_h[idx & 63]);
    // x buf 0 (t=0) + pt buf 0; prefetch t=1
    float pv = 0.f, tv = 0.f;
    if (tid < CPB) {
        float p0 = precip[cellbase + tid], t0 = temp[cellbase + tid];
        *(uint4*)(sm + X16 + tid * 16) =
            make_uint4(pk(f2h(p0), f2h(t0)), pk(0x3C00, 0), 0, 0);  // 1.0h
        ptb[tid] = make_float2(p0, t0);
        pv = precip[NCELL + cellbase + tid];
        tv = temp[NCELL + cellbase + tid];
    }
    __syncthreads();

    const u32 ah_lm = sb + H16 + (u32)((lane & 15) * 144 + (lane >> 4) * 16);
    const u32 ax_lm = sb + X16 + (u32)((lane & 15) * 16);

    for (int t = 0; t < TST; ++t) {
        const int pr = t & 1, nx = (t + 1) & 1;
        const u32 ah_b = ah_lm + (u32)(pr * 9216);
        const u32 ax_b = ax_lm + (u32)(pr * 1024);

        // ---- staging warps: x(t+1), pt(t+1), y-reduce(t-1), prefetch(t+2) ----
        if (tid < CPB) {
            *(uint4*)(sm + X16 + nx * 1024 + tid * 16) =
                make_uint4(pk(f2h(pv), f2h(tv)), pk(0x3C00, 0), 0, 0);
            ptb[nx * CPB + tid] = make_float2(pv, tv);
            int tn = (t + 2 < TST) ? t + 2 : TST - 1;
            pv = precip[tn * NCELL + cellbase + tid];
            tv = temp[tn * NCELL + cellbase + tid];
            if (t > 0) {
                float y = ob;
                const float* yb = ybuf + ((t - 1) & 1) * 512;
#pragma unroll
                for (int w = 0; w < 8; ++w) y += yb[w * CPB + tid];
                out[(t - 1) * NCELL + cellbase + tid] = y;
            }
        }

        u16* h16w = h16 + nx * 4608;
        const float2* ptc = ptb + pr * CPB;
        float* yb = ybuf + pr * 512;

        // ---- mt-major: MMA(mt) immediately followed by epilogue(mt); the
        //      scheduler interleaves epilogue(mt) with MMA(mt+1) (independent)
#pragma unroll
        for (int mt = 0; mt < 4; ++mt) {
            float d[3][4];
#pragma unroll
            for (int gr = 0; gr < 3; ++gr)
#pragma unroll
                for (int q = 0; q < 4; ++q) d[gr][q] = 0.f;

#pragma unroll
            for (int c = 0; c < 4; ++c) {
                u32 a[4];
                LDSM4(a, ah_b + mt * 2304 + c * 32);
                HMMA16(d[0], a, Bh[0][c][0], Bh[0][c][1]);
                HMMA16(d[1], a, Bh[1][c][0], Bh[1][c][1]);
                HMMA16(d[2], a, Bh[2][c][0], Bh[2][c][1]);
            }
            {
                u32 ax[2];
                LDSM2(ax, ax_b + mt * 256);
                HMMA8(d[0], ax, Bx[0]);
                HMMA8(d[1], ax, Bx[1]);
                HMMA8(d[2], ax, Bx[2]);       // bias_n into candidate pre-act
            }

            // ---- epilogue(mt): writes hbuf[nx] (disjoint from MMA reads) ----
#pragma unroll
            for (int hf = 0; hf < 2; ++hf) {
                const int cell = mt * 16 + g + hf * 8;
                const int u = mt * 4 + hf * 2;
                float2 xv = ptc[cell];
                float Dr0 = d[0][2 * hf], Dr1 = d[0][2 * hf + 1];
                float Dz0 = d[1][2 * hf], Dz1 = d[1][2 * hf + 1];
                float Dn0 = d[2][2 * hf], Dn1 = d[2][2 * hf + 1];
                float2 rr = sigm2_fast(Dr0, Dr1);
                float2 zz = sigm2_fast(Dz0, Dz1);
                float ig0 = fmaf(wp0, xv.x, fmaf(wt0, xv.y, bb0));
                float ig1 = fmaf(wp1, xv.x, fmaf(wt1, xv.y, bb1));
                float n0 = tanha(fmaf(rr.x, Dn0, ig0));   // bn already in Dn
                float n1 = tanha(fmaf(rr.y, Dn1, ig1));
                float h0 = fmaf(zz.x, hreg[u] - n0, n0);
                float h1 = fmaf(zz.y, hreg[u + 1] - n1, n1);
                hreg[u] = h0; hreg[u + 1] = h1;
                *(u32*)&h16w[cell * 72 + k0] = pk(f2h(h0), f2h(h1));
                float yq = fmaf(ow0, h0, ow1 * h1);
                yq += __shfl_xor_sync(0xffffffffu, yq, 1);
                yq += __shfl_xor_sync(0xffffffffu, yq, 2);
                if (c4 == 0) yb[wid * CPB + cell] = yq;
            }
        }
        __syncthreads();   // single barrier per step
    }

    // trailing y reduce for t = TST-1
    if (tid < CPB) {
        float y = ob;
        const float* yb = ybuf + ((TST - 1) & 1) * 512;
#pragma unroll
        for (int w = 0; w < 8; ++w) y += yb[w * CPB + tid];
        out[(TST - 1) * NCELL + cellbase + tid] = y;
    }

    // ---- final hidden state (exact fp32 from regs) ----
#pragma unroll
    for (int u = 0; u < 16; ++u) {
        int cell = (u >> 2) * 16 + g + ((u >> 1) & 1) * 8;
        int k = k0 + (u & 1);
        out[(long long)TST * NCELL + (long long)(cellbase + cell) * 64 + k] = hreg[u];
    }
}

extern "C" void kernel_launch(void* const* d_in, const int* in_sizes, int n_in,
                              void* d_out, int out_size) {
    const float* precip = (const float*)d_in[0];
    const float* temp   = (const float*)d_in[1];
    const float* w_ih   = (const float*)d_in[2];
    const float* w_hh   = (const float*)d_in[3];
    const float* bias   = (const float*)d_in[4];
    const float* bias_n = (const float*)d_in[5];
    const float* out_w  = (const float*)d_in[6];
    const float* out_b  = (const float*)d_in[7];
    const float* init_h = (const float*)d_in[8];
    float* out = (float*)d_out;

    gru_f16_kernel<<<NBLK, 256, SMB>>>(
        precip, temp, w_ih, w_hh, bias, bias_n, out_w, out_b, init_h, out);
}